// round 7
// baseline (speedup 1.0000x reference)
#include <cuda_runtime.h>
#include <cuda_bf16.h>
#include <math.h>
#include <cstdint>

// ---------------- problem constants ----------------
#define B_  2
#define L_  2048
#define D_  1024
#define NL_ 8
#define DFF_ 4096
#define H_  16
#define DH_ 64
#define WIN_ 1024
#define M_  (B_*L_)       // 4096 rows

// ---------------- scratch (device globals; no runtime alloc) ----------------
__device__ float g_res [M_*D_];
__device__ float g_qkv [M_*3*D_];
__device__ float g_a   [M_*D_];
__device__ float g_gbuf[M_*2*DFF_];
__device__ float g_x   [M_*D_];
__device__ float g_cos [L_*32];
__device__ float g_sin [L_*32];

__device__ __nv_bfloat16 g_hn_hi [M_*D_],   g_hn_lo [M_*D_];
__device__ __nv_bfloat16 g_ctx_hi[M_*D_],   g_ctx_lo[M_*D_];
__device__ __nv_bfloat16 g_sw_hi [M_*DFF_], g_sw_lo [M_*DFF_];

__device__ __nv_bfloat16 g_wqkv_hi[NL_*3*D_*D_],  g_wqkv_lo[NL_*3*D_*D_];
__device__ __nv_bfloat16 g_wout_hi[NL_*D_*D_],    g_wout_lo[NL_*D_*D_];
__device__ __nv_bfloat16 g_fc1_hi [NL_*2*DFF_*D_],g_fc1_lo [NL_*2*DFF_*D_];
__device__ __nv_bfloat16 g_fc2_hi [NL_*D_*DFF_],  g_fc2_lo [NL_*D_*DFF_];

// ---------------- helpers ----------------
__device__ __forceinline__ uint32_t smem_u32(const void* p) {
    uint32_t a;
    asm("{ .reg .u64 t; cvta.to.shared.u64 t, %1; cvt.u32.u64 %0, t; }" : "=r"(a) : "l"(p));
    return a;
}
__device__ __forceinline__ void cp16(uint32_t dst, const void* src) {
    asm volatile("cp.async.cg.shared.global [%0], [%1], 16;" :: "r"(dst), "l"(src));
}
#define CP_COMMIT() asm volatile("cp.async.commit_group;" ::: "memory")
#define CP_WAIT0()  asm volatile("cp.async.wait_group 0;" ::: "memory")

#define SWZ(x) ((x) ^ (((x) >> 3) & 0x70))

#define LDM_X4(r, a)                                                           \
    asm volatile("ldmatrix.sync.aligned.m8n8.x4.shared.b16 {%0,%1,%2,%3}, [%4];" \
        : "=r"((r)[0]), "=r"((r)[1]), "=r"((r)[2]), "=r"((r)[3]) : "r"(a))

#define MMA(d, a, b0, b1)                                                      \
    asm volatile("mma.sync.aligned.m16n8k16.row.col.f32.bf16.bf16.f32 "        \
        "{%0,%1,%2,%3},{%4,%5,%6,%7},{%8,%9},{%0,%1,%2,%3};"                   \
        : "+f"((d)[0]), "+f"((d)[1]), "+f"((d)[2]), "+f"((d)[3])               \
        : "r"((a)[0]), "r"((a)[1]), "r"((a)[2]), "r"((a)[3]), "r"(b0), "r"(b1))

// ---------------- HMMA GEMM: C[M,N] = A@W^T, split-bf16 (3 fused passes) -----
// CTA tile 128x256, BK=64, 256 threads (8 warps, 2m x 4n), warp tile 64x64.
#define SZ_A  16384                      // 128 rows x 128B
#define SZ_W  32768                      // 256 rows x 128B
#define STAGE_BYTES (2*SZ_A + 2*SZ_W)    // 98304
#define OFF_AH 0
#define OFF_AL SZ_A
#define OFF_WH (2*SZ_A)
#define OFF_WL (2*SZ_A + SZ_W)
#define GEMM_SMEM (2*STAGE_BYTES)        // 196608

__device__ __forceinline__ void gemm_load_stage(
    uint32_t sb_stage,
    const __nv_bfloat16* __restrict__ Ah, const __nv_bfloat16* __restrict__ Al,
    const __nv_bfloat16* __restrict__ Wh, const __nv_bfloat16* __restrict__ Wl,
    int bm, int bn, int k0, int K, int tid)
{
    // A: 2 tiles x 128 rows x 8 segs = 2048 cp16
#pragma unroll
    for (int n = 0; n < 8; n++) {
        int idx = tid + n * 256;
        int tile = idx >> 10;
        int r = (idx >> 3) & 127;
        int seg = idx & 7;
        const __nv_bfloat16* base = tile ? Al : Ah;
        const void* src = base + (size_t)(bm + r) * K + k0 + seg * 8;
        cp16(sb_stage + tile * SZ_A + SWZ(r * 128 + seg * 16), src);
    }
    // W: 2 tiles x 256 rows x 8 segs = 4096 cp16
#pragma unroll
    for (int n = 0; n < 16; n++) {
        int idx = tid + n * 256;
        int tile = idx >> 11;
        int r = (idx >> 3) & 255;
        int seg = idx & 7;
        const __nv_bfloat16* base = tile ? Wl : Wh;
        const void* src = base + (size_t)(bn + r) * K + k0 + seg * 8;
        cp16(sb_stage + OFF_WH + tile * SZ_W + SWZ(r * 128 + seg * 16), src);
    }
}

__global__ __launch_bounds__(256, 1) void gemm_mma(
    const __nv_bfloat16* __restrict__ Ah, const __nv_bfloat16* __restrict__ Al,
    const __nv_bfloat16* __restrict__ Wh, const __nv_bfloat16* __restrict__ Wl,
    float* __restrict__ C, int N, int K)
{
    extern __shared__ char smem[];
    uint32_t sb = smem_u32(smem);
    int tid  = threadIdx.x;
    int lane = tid & 31;
    int wid  = tid >> 5;
    int warp_m = wid >> 2;        // 0..1  (64 rows each)
    int warp_n = wid & 3;         // 0..3  (64 cols each)
    int bm = blockIdx.y * 128;
    int bn = blockIdx.x * 256;

    float acc[4][8][4];
#pragma unroll
    for (int i = 0; i < 4; i++)
#pragma unroll
        for (int j = 0; j < 8; j++)
#pragma unroll
            for (int r = 0; r < 4; r++) acc[i][j][r] = 0.f;

    int a_row = warp_m * 64 + (lane & 15);
    int a_seg_off = (lane >> 4);
    int b_row = warp_n * 64 + (lane & 7) + ((lane & 16) >> 1);
    int b_seg_off = (lane >> 3) & 1;

    int chunks = K >> 6;
    gemm_load_stage(sb, Ah, Al, Wh, Wl, bm, bn, 0, K, tid);
    CP_COMMIT();

    for (int ch = 0; ch < chunks; ch++) {
        CP_WAIT0();
        __syncthreads();
        uint32_t stage = sb + (ch & 1) * STAGE_BYTES;
        if (ch + 1 < chunks) {
            gemm_load_stage(sb + ((ch + 1) & 1) * STAGE_BYTES,
                            Ah, Al, Wh, Wl, bm, bn, (ch + 1) * 64, K, tid);
            CP_COMMIT();
        }
#pragma unroll
        for (int ks = 0; ks < 4; ks++) {
            uint32_t ah[4][4], al[4][4], wb[4][4], wl[4][4];
#pragma unroll
            for (int i = 0; i < 4; i++) {
                int row = a_row + i * 16;
                uint32_t off = SWZ(row * 128 + (2 * ks + a_seg_off) * 16);
                LDM_X4(ah[i], stage + OFF_AH + off);
                LDM_X4(al[i], stage + OFF_AL + off);
            }
#pragma unroll
            for (int g = 0; g < 4; g++) {
                int row = b_row + g * 16;
                uint32_t off = SWZ(row * 128 + (2 * ks + b_seg_off) * 16);
                LDM_X4(wb[g], stage + OFF_WH + off);
            }
            // pass 1: Ah * Wh
#pragma unroll
            for (int i = 0; i < 4; i++)
#pragma unroll
                for (int j = 0; j < 8; j++)
                    MMA(acc[i][j], ah[i], wb[j >> 1][(j & 1) * 2], wb[j >> 1][(j & 1) * 2 + 1]);
            // pass 2: Al * Wh (al dies after this)
#pragma unroll
            for (int i = 0; i < 4; i++)
#pragma unroll
                for (int j = 0; j < 8; j++)
                    MMA(acc[i][j], al[i], wb[j >> 1][(j & 1) * 2], wb[j >> 1][(j & 1) * 2 + 1]);
            // load Wl (reuses wb's register budget once wb dies below)
#pragma unroll
            for (int g = 0; g < 4; g++) {
                int row = b_row + g * 16;
                uint32_t off = SWZ(row * 128 + (2 * ks + b_seg_off) * 16);
                LDM_X4(wl[g], stage + OFF_WL + off);
            }
            // pass 3: Ah * Wl
#pragma unroll
            for (int i = 0; i < 4; i++)
#pragma unroll
                for (int j = 0; j < 8; j++)
                    MMA(acc[i][j], ah[i], wl[j >> 1][(j & 1) * 2], wl[j >> 1][(j & 1) * 2 + 1]);
        }
        __syncthreads();
    }

    // epilogue: direct STG (float2 per fragment row)
#pragma unroll
    for (int i = 0; i < 4; i++) {
        int r0 = bm + warp_m * 64 + i * 16 + (lane >> 2);
#pragma unroll
        for (int j = 0; j < 8; j++) {
            int c = bn + warp_n * 64 + (j >> 1) * 16 + (j & 1) * 8 + (lane & 3) * 2;
            *(float2*)&C[(size_t)r0 * N + c]       = make_float2(acc[i][j][0], acc[i][j][1]);
            *(float2*)&C[(size_t)(r0 + 8) * N + c] = make_float2(acc[i][j][2], acc[i][j][3]);
        }
    }
}

// ---------------- weight fp32 -> bf16 hi/lo split ----------------
__global__ void cvt_kernel(const float* __restrict__ src,
                           __nv_bfloat16* __restrict__ hi,
                           __nv_bfloat16* __restrict__ lo, int n) {
    int i = blockIdx.x * 256 + threadIdx.x;
    if (i >= n) return;
    float v = src[i];
    __nv_bfloat16 h = __float2bfloat16(v);
    hi[i] = h;
    lo[i] = __float2bfloat16(v - __bfloat162float(h));
}

// ---------------- rope tables ----------------
__global__ void rope_table_kernel() {
    int idx = blockIdx.x * blockDim.x + threadIdx.x;
    if (idx >= L_ * 32) return;
    int pos = idx >> 5;
    int j = idx & 31;
    float e   = (float)(2 * j) / 64.0f;
    float inv = 1.0f / powf(10000.0f, e);
    float fr  = (float)pos * inv;
    g_cos[idx] = (float)cos((double)fr);
    g_sin[idx] = (float)sin((double)fr);
}

// ---------------- fused (x [+res]) -> res, rms*w -> hn (bf16 hi/lo or fp32) ----
template<int BF>
__global__ void add_rms_kernel(const float* __restrict__ x,
                               const float* __restrict__ res_in,
                               float* __restrict__ res_out,
                               __nv_bfloat16* __restrict__ hh,
                               __nv_bfloat16* __restrict__ hl,
                               float* __restrict__ hf,
                               const float* __restrict__ w,
                               int useRes) {
    int row = blockIdx.x;
    int tid = threadIdx.x;
    const float* xr = x + (size_t)row * D_;
    const float* rr = res_in + (size_t)row * D_;
    float h[4];
    float ss = 0.f;
#pragma unroll
    for (int i = 0; i < 4; i++) {
        int c = tid + i * 256;
        float v = xr[c];
        if (useRes) v += rr[c];
        h[i] = v;
        ss += v * v;
    }
#pragma unroll
    for (int o = 16; o; o >>= 1) ss += __shfl_xor_sync(0xffffffffu, ss, o);
    __shared__ float red[8];
    if ((tid & 31) == 0) red[tid >> 5] = ss;
    __syncthreads();
    float tot = 0.f;
#pragma unroll
    for (int i = 0; i < 8; i++) tot += red[i];
    float scale = rsqrtf(tot * (1.0f / (float)D_) + 1e-5f);
#pragma unroll
    for (int i = 0; i < 4; i++) {
        int c = tid + i * 256;
        res_out[(size_t)row * D_ + c] = h[i];
        float hv = h[i] * scale * w[c];
        if (BF) {
            __nv_bfloat16 hi = __float2bfloat16(hv);
            hh[(size_t)row * D_ + c] = hi;
            hl[(size_t)row * D_ + c] = __float2bfloat16(hv - __bfloat162float(hi));
        } else {
            hf[(size_t)row * D_ + c] = hv;
        }
    }
}

// ---------------- RoPE on q,k inside qkv buffer ----------------
__global__ void rope_kernel(float* __restrict__ qkv) {
    int idx = blockIdx.x * blockDim.x + threadIdx.x;
    int j  = idx & 31;
    int hh = (idx >> 5) & 15;
    int m  = idx >> 9;
    if (m >= M_) return;
    int pos = m & (L_ - 1);
    float c  = g_cos[pos * 32 + j];
    float sn = g_sin[pos * 32 + j];
    size_t base = (size_t)m * (3 * D_) + hh * DH_ + j;
    float u1 = qkv[base], u2 = qkv[base + 32];
    qkv[base]      = u1 * c - u2 * sn;
    qkv[base + 32] = u2 * c + u1 * sn;
    float v1 = qkv[base + D_], v2 = qkv[base + D_ + 32];
    qkv[base + D_]      = v1 * c - v2 * sn;
    qkv[base + D_ + 32] = v2 * c + v1 * sn;
}

// ---------------- flash-tiled sliding-window attention ----------------
#define ATT_PITCH 68
#define ATT_SMEM ((4*64*ATT_PITCH + 192) * 4)

__global__ __launch_bounds__(256) void attn_flash(const float* __restrict__ qkv,
                                                  __nv_bfloat16* __restrict__ ctxh,
                                                  __nv_bfloat16* __restrict__ ctxl) {
    extern __shared__ float sm[];
    float* Qt = sm;
    float* Kt = sm + 64 * ATT_PITCH;
    float* Vs = sm + 2 * 64 * ATT_PITCH;
    float* St = sm + 3 * 64 * ATT_PITCH;
    float* mrow = sm + 4 * 64 * ATT_PITCH;
    float* lrow = mrow + 64;
    float* arow = mrow + 128;

    int qbase = blockIdx.x * 64;
    int h = blockIdx.y, b = blockIdx.z;
    int tid = threadIdx.x;
    const int RS = 3 * D_;
    const float* qk_base = qkv + (size_t)b * L_ * RS + h * DH_;

#pragma unroll
    for (int j = 0; j < 4; j++) {
        int idx = tid + 256 * j;
        int tok = idx >> 4;
        int d0  = (idx & 15) * 4;
        float4 v = *(const float4*)(qk_base + (size_t)(qbase + tok) * RS + d0);
        Qt[(d0 + 0) * ATT_PITCH + tok] = v.x * 0.125f;
        Qt[(d0 + 1) * ATT_PITCH + tok] = v.y * 0.125f;
        Qt[(d0 + 2) * ATT_PITCH + tok] = v.z * 0.125f;
        Qt[(d0 + 3) * ATT_PITCH + tok] = v.w * 0.125f;
    }
    if (tid < 64) { mrow[tid] = -INFINITY; lrow[tid] = 0.f; }

    int r0 = (tid >> 4) * 4;
    int c0 = (tid & 15) * 4;
    float o[4][4];
#pragma unroll
    for (int i = 0; i < 4; i++)
#pragma unroll
        for (int j = 0; j < 4; j++) o[i][j] = 0.f;

    int klo = qbase - (WIN_ - 1); if (klo < 0) klo = 0;
    int kt0 = klo & ~63;

    for (int kt = kt0; kt < qbase + 64; kt += 64) {
        __syncthreads();
#pragma unroll
        for (int j = 0; j < 4; j++) {
            int idx = tid + 256 * j;
            int tok = idx >> 4;
            int d0  = (idx & 15) * 4;
            const float* row = qk_base + (size_t)(kt + tok) * RS + D_;
            float4 kv = *(const float4*)(row + d0);
            Kt[(d0 + 0) * ATT_PITCH + tok] = kv.x;
            Kt[(d0 + 1) * ATT_PITCH + tok] = kv.y;
            Kt[(d0 + 2) * ATT_PITCH + tok] = kv.z;
            Kt[(d0 + 3) * ATT_PITCH + tok] = kv.w;
            float4 vv = *(const float4*)(row + D_ + d0);
            *(float4*)&Vs[tok * ATT_PITCH + d0] = vv;
        }
        __syncthreads();

        float s[4][4];
#pragma unroll
        for (int i = 0; i < 4; i++)
#pragma unroll
            for (int j = 0; j < 4; j++) s[i][j] = 0.f;
#pragma unroll
        for (int d = 0; d < 64; d++) {
            float4 qv = *(float4*)&Qt[d * ATT_PITCH + r0];
            float4 kv = *(float4*)&Kt[d * ATT_PITCH + c0];
            float qa[4] = {qv.x, qv.y, qv.z, qv.w};
            float ka[4] = {kv.x, kv.y, kv.z, kv.w};
#pragma unroll
            for (int i = 0; i < 4; i++)
#pragma unroll
                for (int j = 0; j < 4; j++) s[i][j] += qa[i] * ka[j];
        }
#pragma unroll
        for (int i = 0; i < 4; i++) {
            int qg = qbase + r0 + i;
#pragma unroll
            for (int j = 0; j < 4; j++) {
                int kg = kt + c0 + j;
                bool ok = (kg <= qg) && (kg >= qg - (WIN_ - 1));
                St[(c0 + j) * ATT_PITCH + r0 + i] = ok ? s[i][j] : -INFINITY;
            }
        }
        __syncthreads();

        {
            int row = tid >> 2;
            int part = tid & 3;
            float tmax = -INFINITY;
#pragma unroll
            for (int k = 0; k < 16; k++)
                tmax = fmaxf(tmax, St[(part * 16 + k) * ATT_PITCH + row]);
            tmax = fmaxf(tmax, __shfl_xor_sync(0xffffffffu, tmax, 1));
            tmax = fmaxf(tmax, __shfl_xor_sync(0xffffffffu, tmax, 2));
            float mold = mrow[row];
            float mnew = fmaxf(mold, tmax);
            float msafe = (mnew == -INFINITY) ? 0.f : mnew;
            float alpha = expf(mold - msafe);
            float lsum = 0.f;
#pragma unroll
            for (int k = 0; k < 16; k++) {
                float* sp = &St[(part * 16 + k) * ATT_PITCH + row];
                float p = expf(*sp - msafe);
                *sp = p;
                lsum += p;
            }
            lsum += __shfl_xor_sync(0xffffffffu, lsum, 1);
            lsum += __shfl_xor_sync(0xffffffffu, lsum, 2);
            if (part == 0) {
                mrow[row] = mnew;
                lrow[row] = alpha * lrow[row] + lsum;
                arow[row] = alpha;
            }
        }
        __syncthreads();

        float al[4];
#pragma unroll
        for (int i = 0; i < 4; i++) al[i] = arow[r0 + i];
#pragma unroll
        for (int i = 0; i < 4; i++)
#pragma unroll
            for (int j = 0; j < 4; j++) o[i][j] *= al[i];
#pragma unroll
        for (int kk = 0; kk < 64; kk++) {
            float4 pv = *(float4*)&St[kk * ATT_PITCH + r0];
            float4 vv = *(float4*)&Vs[kk * ATT_PITCH + c0];
            float pa[4] = {pv.x, pv.y, pv.z, pv.w};
            float va[4] = {vv.x, vv.y, vv.z, vv.w};
#pragma unroll
            for (int i = 0; i < 4; i++)
#pragma unroll
                for (int j = 0; j < 4; j++) o[i][j] += pa[i] * va[j];
        }
    }
    __syncthreads();

#pragma unroll
    for (int i = 0; i < 4; i++) {
        float inv = 1.f / lrow[r0 + i];
        size_t off = (size_t)(b * L_ + qbase + r0 + i) * D_ + h * DH_ + c0;
#pragma unroll
        for (int j = 0; j < 4; j++) {
            float val = o[i][j] * inv;
            __nv_bfloat16 hi = __float2bfloat16(val);
            ctxh[off + j] = hi;
            ctxl[off + j] = __float2bfloat16(val - __bfloat162float(hi));
        }
    }
}

// ---------------- SwiGLU -> bf16 hi/lo ----------------
__global__ void swiglu_kernel(const float* __restrict__ g,
                              __nv_bfloat16* __restrict__ swh,
                              __nv_bfloat16* __restrict__ swl) {
    int idx = blockIdx.x * blockDim.x + threadIdx.x;
    if (idx >= M_ * DFF_) return;
    int m = idx >> 12;
    int c = idx & 4095;
    float a  = g[(size_t)m * (2 * DFF_) + c];
    float b2 = g[(size_t)m * (2 * DFF_) + DFF_ + c];
    float sig = 1.0f / (1.0f + expf(-a));
    float v = a * sig * b2;
    __nv_bfloat16 hi = __float2bfloat16(v);
    swh[idx] = hi;
    swl[idx] = __float2bfloat16(v - __bfloat162float(hi));
}

// ---------------- host launch ----------------
extern "C" void kernel_launch(void* const* d_in, const int* in_sizes, int n_in,
                              void* d_out, int out_size) {
    const float* x_in = (const float*)d_in[0];
    const float* Wqkv = (const float*)d_in[2];
    const float* Wout = (const float*)d_in[3];
    const float* fc1  = (const float*)d_in[4];
    const float* fc2  = (const float*)d_in[5];
    const float* n1w  = (const float*)d_in[6];
    const float* n2w  = (const float*)d_in[7];
    const float* nfw  = (const float*)d_in[8];
    float* out = (float*)d_out;

    float *res, *qkv, *a, *g, *xb;
    __nv_bfloat16 *hnh, *hnl, *cth, *ctl, *swh, *swl;
    __nv_bfloat16 *wqh, *wql, *woh, *wol, *f1h, *f1l, *f2h, *f2l;
    cudaGetSymbolAddress((void**)&res, g_res);
    cudaGetSymbolAddress((void**)&qkv, g_qkv);
    cudaGetSymbolAddress((void**)&a,   g_a);
    cudaGetSymbolAddress((void**)&g,   g_gbuf);
    cudaGetSymbolAddress((void**)&xb,  g_x);
    cudaGetSymbolAddress((void**)&hnh, g_hn_hi);
    cudaGetSymbolAddress((void**)&hnl, g_hn_lo);
    cudaGetSymbolAddress((void**)&cth, g_ctx_hi);
    cudaGetSymbolAddress((void**)&ctl, g_ctx_lo);
    cudaGetSymbolAddress((void**)&swh, g_sw_hi);
    cudaGetSymbolAddress((void**)&swl, g_sw_lo);
    cudaGetSymbolAddress((void**)&wqh, g_wqkv_hi);
    cudaGetSymbolAddress((void**)&wql, g_wqkv_lo);
    cudaGetSymbolAddress((void**)&woh, g_wout_hi);
    cudaGetSymbolAddress((void**)&wol, g_wout_lo);
    cudaGetSymbolAddress((void**)&f1h, g_fc1_hi);
    cudaGetSymbolAddress((void**)&f1l, g_fc1_lo);
    cudaGetSymbolAddress((void**)&f2h, g_fc2_hi);
    cudaGetSymbolAddress((void**)&f2l, g_fc2_lo);

    cudaFuncSetAttribute(gemm_mma, cudaFuncAttributeMaxDynamicSharedMemorySize, GEMM_SMEM);
    cudaFuncSetAttribute(attn_flash, cudaFuncAttributeMaxDynamicSharedMemorySize, ATT_SMEM);

    {
        int n;
        n = NL_*3*D_*D_;   cvt_kernel<<<(n+255)/256, 256>>>(Wqkv, wqh, wql, n);
        n = NL_*D_*D_;     cvt_kernel<<<(n+255)/256, 256>>>(Wout, woh, wol, n);
        n = NL_*2*DFF_*D_; cvt_kernel<<<(n+255)/256, 256>>>(fc1,  f1h, f1l, n);
        n = NL_*D_*DFF_;   cvt_kernel<<<(n+255)/256, 256>>>(fc2,  f2h, f2l, n);
    }
    rope_table_kernel<<<(L_*32 + 255)/256, 256>>>();

    const float* cur_x = x_in;
    for (int l = 0; l < NL_; l++) {
        add_rms_kernel<1><<<M_, 256>>>(cur_x, res, res, hnh, hnl, nullptr,
                                       n1w + (size_t)l*D_, l > 0);
        gemm_mma<<<dim3(3*D_/256, M_/128), 256, GEMM_SMEM>>>(
            hnh, hnl, wqh + (size_t)l*3*D_*D_, wql + (size_t)l*3*D_*D_, qkv, 3*D_, D_);
        rope_kernel<<<(M_*H_*32)/256, 256>>>(qkv);
        attn_flash<<<dim3(L_/64, H_, B_), 256, ATT_SMEM>>>(qkv, cth, ctl);
        gemm_mma<<<dim3(D_/256, M_/128), 256, GEMM_SMEM>>>(
            cth, ctl, woh + (size_t)l*D_*D_, wol + (size_t)l*D_*D_, a, D_, D_);
        add_rms_kernel<1><<<M_, 256>>>(a, res, res, hnh, hnl, nullptr,
                                       n2w + (size_t)l*D_, 1);
        gemm_mma<<<dim3(2*DFF_/256, M_/128), 256, GEMM_SMEM>>>(
            hnh, hnl, f1h + (size_t)l*2*DFF_*D_, f1l + (size_t)l*2*DFF_*D_, g, 2*DFF_, D_);
        swiglu_kernel<<<(M_*DFF_)/256, 256>>>(g, swh, swl);
        gemm_mma<<<dim3(D_/256, M_/128), 256, GEMM_SMEM>>>(
            swh, swl, f2h + (size_t)l*D_*DFF_, f2l + (size_t)l*D_*DFF_, xb, D_, DFF_);
        cur_x = xb;
    }
    add_rms_kernel<0><<<M_, 256>>>(cur_x, res, res, nullptr, nullptr, out, nfw, 1);
}

// round 8
// speedup vs baseline: 1.0114x; 1.0114x over previous
#include <cuda_runtime.h>
#include <cuda_bf16.h>
#include <math.h>
#include <cstdint>

// ---------------- problem constants ----------------
#define B_  2
#define L_  2048
#define D_  1024
#define NL_ 8
#define DFF_ 4096
#define H_  16
#define DH_ 64
#define WIN_ 1024
#define M_  (B_*L_)       // 4096 rows

// ---------------- scratch (device globals; no runtime alloc) ----------------
__device__ float g_res [M_*D_];
__device__ float g_qkv [M_*3*D_];
__device__ float g_a   [M_*D_];
__device__ float g_gbuf[M_*2*DFF_];
__device__ float g_x   [M_*D_];
__device__ float g_cos [L_*32];
__device__ float g_sin [L_*32];

__device__ __nv_bfloat16 g_hn_hi [M_*D_],   g_hn_lo [M_*D_];
__device__ __nv_bfloat16 g_ctx_hi[M_*D_],   g_ctx_lo[M_*D_];
__device__ __nv_bfloat16 g_sw_hi [M_*DFF_], g_sw_lo [M_*DFF_];

__device__ __nv_bfloat16 g_wqkv_hi[NL_*3*D_*D_],  g_wqkv_lo[NL_*3*D_*D_];
__device__ __nv_bfloat16 g_wout_hi[NL_*D_*D_],    g_wout_lo[NL_*D_*D_];
__device__ __nv_bfloat16 g_fc1_hi [NL_*2*DFF_*D_],g_fc1_lo [NL_*2*DFF_*D_];
__device__ __nv_bfloat16 g_fc2_hi [NL_*D_*DFF_],  g_fc2_lo [NL_*D_*DFF_];

// ---------------- helpers ----------------
__device__ __forceinline__ uint32_t smem_u32(const void* p) {
    uint32_t a;
    asm("{ .reg .u64 t; cvta.to.shared.u64 t, %1; cvt.u32.u64 %0, t; }" : "=r"(a) : "l"(p));
    return a;
}
__device__ __forceinline__ void cp16(uint32_t dst, const void* src) {
    asm volatile("cp.async.cg.shared.global [%0], [%1], 16;" :: "r"(dst), "l"(src));
}
#define CP_COMMIT() asm volatile("cp.async.commit_group;" ::: "memory")
#define CP_WAIT1()  asm volatile("cp.async.wait_group 1;" ::: "memory")

#define SWZ(x) ((x) ^ (((x) >> 3) & 0x70))

#define LDM_X4(r, a)                                                           \
    asm volatile("ldmatrix.sync.aligned.m8n8.x4.shared.b16 {%0,%1,%2,%3}, [%4];" \
        : "=r"((r)[0]), "=r"((r)[1]), "=r"((r)[2]), "=r"((r)[3]) : "r"(a))

#define MMA(d, a, b0, b1)                                                      \
    asm volatile("mma.sync.aligned.m16n8k16.row.col.f32.bf16.bf16.f32 "        \
        "{%0,%1,%2,%3},{%4,%5,%6,%7},{%8,%9},{%0,%1,%2,%3};"                   \
        : "+f"((d)[0]), "+f"((d)[1]), "+f"((d)[2]), "+f"((d)[3])               \
        : "r"((a)[0]), "r"((a)[1]), "r"((a)[2]), "r"((a)[3]), "r"(b0), "r"(b1))

// ---------------- HMMA GEMM: C[M,N] = A@W^T, split-bf16 (3 fused passes) -----
// CTA tile 128x128, BK=64, 256 threads (8 warps, 2m x 4n), warp tile 64x32.
// 3-stage cp.async pipeline, wait_group 1, one barrier per chunk.
#define TILE_BYTES 16384                 // 128 rows x 128B
#define STAGE_BYTES (4*TILE_BYTES)       // Ah, Al, Wh, Wl = 65536
#define GEMM_SMEM  (3*STAGE_BYTES)       // 196608

__device__ __forceinline__ void gemm_load_stage(
    uint32_t sb_stage,
    const __nv_bfloat16* __restrict__ Ah, const __nv_bfloat16* __restrict__ Al,
    const __nv_bfloat16* __restrict__ Wh, const __nv_bfloat16* __restrict__ Wl,
    int bm, int bn, int k0, int K, int tid)
{
    const __nv_bfloat16* bases[4] = { Ah + (size_t)bm * K, Al + (size_t)bm * K,
                                      Wh + (size_t)bn * K, Wl + (size_t)bn * K };
#pragma unroll
    for (int t = 0; t < 4; t++) {
        const __nv_bfloat16* base = bases[t];
#pragma unroll
        for (int q = 0; q < 4; q++) {
            int idx = tid + q * 256;          // 0..1023
            int row = idx >> 3;
            int seg = idx & 7;
            const void* src = base + (size_t)row * K + k0 + seg * 8;
            uint32_t dst = sb_stage + t * TILE_BYTES + SWZ(row * 128 + seg * 16);
            cp16(dst, src);
        }
    }
}

__global__ __launch_bounds__(256, 1) void gemm_mma(
    const __nv_bfloat16* __restrict__ Ah, const __nv_bfloat16* __restrict__ Al,
    const __nv_bfloat16* __restrict__ Wh, const __nv_bfloat16* __restrict__ Wl,
    float* __restrict__ C, int N, int K)
{
    extern __shared__ char smem[];
    uint32_t sb = smem_u32(smem);
    int tid  = threadIdx.x;
    int lane = tid & 31;
    int wid  = tid >> 5;
    int warp_m = wid >> 2;
    int warp_n = wid & 3;
    int bm = blockIdx.y * 128;
    int bn = blockIdx.x * 128;

    float acc[4][4][4];
#pragma unroll
    for (int i = 0; i < 4; i++)
#pragma unroll
        for (int j = 0; j < 4; j++)
#pragma unroll
            for (int r = 0; r < 4; r++) acc[i][j][r] = 0.f;

    int a_row = warp_m * 64 + (lane & 15);
    int a_seg_off = (lane >> 4);
    int b_row = warp_n * 32 + (lane & 7) + ((lane & 16) >> 1);
    int b_seg_off = (lane >> 3) & 1;

    int chunks = K >> 6;
    gemm_load_stage(sb, Ah, Al, Wh, Wl, bm, bn, 0, K, tid);
    CP_COMMIT();
    if (chunks > 1) {
        gemm_load_stage(sb + STAGE_BYTES, Ah, Al, Wh, Wl, bm, bn, 64, K, tid);
    }
    CP_COMMIT();   // always commit (possibly empty) to keep group count aligned

    int st = 0;    // stage index of current chunk
    for (int ch = 0; ch < chunks; ch++) {
        CP_WAIT1();          // stage for chunk ch complete (ch+1 may be in flight)
        __syncthreads();     // all warps done with stage (ch-1) -> its buffer reusable
        if (ch + 2 < chunks) {
            int ns = st + 2; if (ns >= 3) ns -= 3;
            gemm_load_stage(sb + ns * STAGE_BYTES,
                            Ah, Al, Wh, Wl, bm, bn, (ch + 2) * 64, K, tid);
        }
        CP_COMMIT();         // unconditional: keeps pending-group accounting uniform

        uint32_t stage = sb + st * STAGE_BYTES;
#pragma unroll
        for (int ks = 0; ks < 4; ks++) {
            uint32_t ah[4][4], al[4][4], wb[2][4], wl[2][4];
#pragma unroll
            for (int i = 0; i < 4; i++) {
                int row = a_row + i * 16;
                uint32_t off = SWZ(row * 128 + (2 * ks + a_seg_off) * 16);
                LDM_X4(ah[i], stage + off);
                LDM_X4(al[i], stage + TILE_BYTES + off);
            }
#pragma unroll
            for (int j = 0; j < 2; j++) {
                int row = b_row + j * 16;
                uint32_t off = SWZ(row * 128 + (2 * ks + b_seg_off) * 16);
                LDM_X4(wb[j], stage + 2 * TILE_BYTES + off);
                LDM_X4(wl[j], stage + 3 * TILE_BYTES + off);
            }
#pragma unroll
            for (int i = 0; i < 4; i++)
#pragma unroll
                for (int j = 0; j < 4; j++)
                    MMA(acc[i][j], ah[i], wb[j >> 1][(j & 1) * 2], wb[j >> 1][(j & 1) * 2 + 1]);
#pragma unroll
            for (int i = 0; i < 4; i++)
#pragma unroll
                for (int j = 0; j < 4; j++)
                    MMA(acc[i][j], ah[i], wl[j >> 1][(j & 1) * 2], wl[j >> 1][(j & 1) * 2 + 1]);
#pragma unroll
            for (int i = 0; i < 4; i++)
#pragma unroll
                for (int j = 0; j < 4; j++)
                    MMA(acc[i][j], al[i], wb[j >> 1][(j & 1) * 2], wb[j >> 1][(j & 1) * 2 + 1]);
        }
        if (++st == 3) st = 0;
    }

#pragma unroll
    for (int i = 0; i < 4; i++) {
        int r0 = bm + warp_m * 64 + i * 16 + (lane >> 2);
#pragma unroll
        for (int j = 0; j < 4; j++) {
            int c = bn + warp_n * 32 + j * 8 + (lane & 3) * 2;
            *(float2*)&C[(size_t)r0 * N + c]       = make_float2(acc[i][j][0], acc[i][j][1]);
            *(float2*)&C[(size_t)(r0 + 8) * N + c] = make_float2(acc[i][j][2], acc[i][j][3]);
        }
    }
}

// ---------------- weight fp32 -> bf16 hi/lo split ----------------
__global__ void cvt_kernel(const float* __restrict__ src,
                           __nv_bfloat16* __restrict__ hi,
                           __nv_bfloat16* __restrict__ lo, int n) {
    int i = blockIdx.x * 256 + threadIdx.x;
    if (i >= n) return;
    float v = src[i];
    __nv_bfloat16 h = __float2bfloat16(v);
    hi[i] = h;
    lo[i] = __float2bfloat16(v - __bfloat162float(h));
}

// ---------------- rope tables ----------------
__global__ void rope_table_kernel() {
    int idx = blockIdx.x * blockDim.x + threadIdx.x;
    if (idx >= L_ * 32) return;
    int pos = idx >> 5;
    int j = idx & 31;
    float e   = (float)(2 * j) / 64.0f;
    float inv = 1.0f / powf(10000.0f, e);
    float fr  = (float)pos * inv;
    g_cos[idx] = (float)cos((double)fr);
    g_sin[idx] = (float)sin((double)fr);
}

// ---------------- fused (x [+res]) -> res, rms*w -> hn (bf16 hi/lo or fp32) ----
template<int BF>
__global__ void add_rms_kernel(const float* __restrict__ x,
                               const float* __restrict__ res_in,
                               float* __restrict__ res_out,
                               __nv_bfloat16* __restrict__ hh,
                               __nv_bfloat16* __restrict__ hl,
                               float* __restrict__ hf,
                               const float* __restrict__ w,
                               int useRes) {
    int row = blockIdx.x;
    int tid = threadIdx.x;
    const float* xr = x + (size_t)row * D_;
    const float* rr = res_in + (size_t)row * D_;
    float h[4];
    float ss = 0.f;
#pragma unroll
    for (int i = 0; i < 4; i++) {
        int c = tid + i * 256;
        float v = xr[c];
        if (useRes) v += rr[c];
        h[i] = v;
        ss += v * v;
    }
#pragma unroll
    for (int o = 16; o; o >>= 1) ss += __shfl_xor_sync(0xffffffffu, ss, o);
    __shared__ float red[8];
    if ((tid & 31) == 0) red[tid >> 5] = ss;
    __syncthreads();
    float tot = 0.f;
#pragma unroll
    for (int i = 0; i < 8; i++) tot += red[i];
    float scale = rsqrtf(tot * (1.0f / (float)D_) + 1e-5f);
#pragma unroll
    for (int i = 0; i < 4; i++) {
        int c = tid + i * 256;
        res_out[(size_t)row * D_ + c] = h[i];
        float hv = h[i] * scale * w[c];
        if (BF) {
            __nv_bfloat16 hi = __float2bfloat16(hv);
            hh[(size_t)row * D_ + c] = hi;
            hl[(size_t)row * D_ + c] = __float2bfloat16(hv - __bfloat162float(hi));
        } else {
            hf[(size_t)row * D_ + c] = hv;
        }
    }
}

// ---------------- RoPE on q,k inside qkv buffer ----------------
__global__ void rope_kernel(float* __restrict__ qkv) {
    int idx = blockIdx.x * blockDim.x + threadIdx.x;
    int j  = idx & 31;
    int hh = (idx >> 5) & 15;
    int m  = idx >> 9;
    if (m >= M_) return;
    int pos = m & (L_ - 1);
    float c  = g_cos[pos * 32 + j];
    float sn = g_sin[pos * 32 + j];
    size_t base = (size_t)m * (3 * D_) + hh * DH_ + j;
    float u1 = qkv[base], u2 = qkv[base + 32];
    qkv[base]      = u1 * c - u2 * sn;
    qkv[base + 32] = u2 * c + u1 * sn;
    float v1 = qkv[base + D_], v2 = qkv[base + D_ + 32];
    qkv[base + D_]      = v1 * c - v2 * sn;
    qkv[base + D_ + 32] = v2 * c + v1 * sn;
}

// ---------------- flash-tiled sliding-window attention ----------------
#define ATT_PITCH 68
#define ATT_SMEM ((4*64*ATT_PITCH + 192) * 4)

__global__ __launch_bounds__(256) void attn_flash(const float* __restrict__ qkv,
                                                  __nv_bfloat16* __restrict__ ctxh,
                                                  __nv_bfloat16* __restrict__ ctxl) {
    extern __shared__ float sm[];
    float* Qt = sm;
    float* Kt = sm + 64 * ATT_PITCH;
    float* Vs = sm + 2 * 64 * ATT_PITCH;
    float* St = sm + 3 * 64 * ATT_PITCH;
    float* mrow = sm + 4 * 64 * ATT_PITCH;
    float* lrow = mrow + 64;
    float* arow = mrow + 128;

    int qbase = blockIdx.x * 64;
    int h = blockIdx.y, b = blockIdx.z;
    int tid = threadIdx.x;
    const int RS = 3 * D_;
    const float* qk_base = qkv + (size_t)b * L_ * RS + h * DH_;

#pragma unroll
    for (int j = 0; j < 4; j++) {
        int idx = tid + 256 * j;
        int tok = idx >> 4;
        int d0  = (idx & 15) * 4;
        float4 v = *(const float4*)(qk_base + (size_t)(qbase + tok) * RS + d0);
        Qt[(d0 + 0) * ATT_PITCH + tok] = v.x * 0.125f;
        Qt[(d0 + 1) * ATT_PITCH + tok] = v.y * 0.125f;
        Qt[(d0 + 2) * ATT_PITCH + tok] = v.z * 0.125f;
        Qt[(d0 + 3) * ATT_PITCH + tok] = v.w * 0.125f;
    }
    if (tid < 64) { mrow[tid] = -INFINITY; lrow[tid] = 0.f; }

    int r0 = (tid >> 4) * 4;
    int c0 = (tid & 15) * 4;
    float o[4][4];
#pragma unroll
    for (int i = 0; i < 4; i++)
#pragma unroll
        for (int j = 0; j < 4; j++) o[i][j] = 0.f;

    int klo = qbase - (WIN_ - 1); if (klo < 0) klo = 0;
    int kt0 = klo & ~63;

    for (int kt = kt0; kt < qbase + 64; kt += 64) {
        __syncthreads();
#pragma unroll
        for (int j = 0; j < 4; j++) {
            int idx = tid + 256 * j;
            int tok = idx >> 4;
            int d0  = (idx & 15) * 4;
            const float* row = qk_base + (size_t)(kt + tok) * RS + D_;
            float4 kv = *(const float4*)(row + d0);
            Kt[(d0 + 0) * ATT_PITCH + tok] = kv.x;
            Kt[(d0 + 1) * ATT_PITCH + tok] = kv.y;
            Kt[(d0 + 2) * ATT_PITCH + tok] = kv.z;
            Kt[(d0 + 3) * ATT_PITCH + tok] = kv.w;
            float4 vv = *(const float4*)(row + D_ + d0);
            *(float4*)&Vs[tok * ATT_PITCH + d0] = vv;
        }
        __syncthreads();

        float s[4][4];
#pragma unroll
        for (int i = 0; i < 4; i++)
#pragma unroll
            for (int j = 0; j < 4; j++) s[i][j] = 0.f;
#pragma unroll
        for (int d = 0; d < 64; d++) {
            float4 qv = *(float4*)&Qt[d * ATT_PITCH + r0];
            float4 kv = *(float4*)&Kt[d * ATT_PITCH + c0];
            float qa[4] = {qv.x, qv.y, qv.z, qv.w};
            float ka[4] = {kv.x, kv.y, kv.z, kv.w};
#pragma unroll
            for (int i = 0; i < 4; i++)
#pragma unroll
                for (int j = 0; j < 4; j++) s[i][j] += qa[i] * ka[j];
        }
#pragma unroll
        for (int i = 0; i < 4; i++) {
            int qg = qbase + r0 + i;
#pragma unroll
            for (int j = 0; j < 4; j++) {
                int kg = kt + c0 + j;
                bool ok = (kg <= qg) && (kg >= qg - (WIN_ - 1));
                St[(c0 + j) * ATT_PITCH + r0 + i] = ok ? s[i][j] : -INFINITY;
            }
        }
        __syncthreads();

        {
            int row = tid >> 2;
            int part = tid & 3;
            float tmax = -INFINITY;
#pragma unroll
            for (int k = 0; k < 16; k++)
                tmax = fmaxf(tmax, St[(part * 16 + k) * ATT_PITCH + row]);
            tmax = fmaxf(tmax, __shfl_xor_sync(0xffffffffu, tmax, 1));
            tmax = fmaxf(tmax, __shfl_xor_sync(0xffffffffu, tmax, 2));
            float mold = mrow[row];
            float mnew = fmaxf(mold, tmax);
            float msafe = (mnew == -INFINITY) ? 0.f : mnew;
            float alpha = expf(mold - msafe);
            float lsum = 0.f;
#pragma unroll
            for (int k = 0; k < 16; k++) {
                float* sp = &St[(part * 16 + k) * ATT_PITCH + row];
                float p = expf(*sp - msafe);
                *sp = p;
                lsum += p;
            }
            lsum += __shfl_xor_sync(0xffffffffu, lsum, 1);
            lsum += __shfl_xor_sync(0xffffffffu, lsum, 2);
            if (part == 0) {
                mrow[row] = mnew;
                lrow[row] = alpha * lrow[row] + lsum;
                arow[row] = alpha;
            }
        }
        __syncthreads();

        float al[4];
#pragma unroll
        for (int i = 0; i < 4; i++) al[i] = arow[r0 + i];
#pragma unroll
        for (int i = 0; i < 4; i++)
#pragma unroll
            for (int j = 0; j < 4; j++) o[i][j] *= al[i];
#pragma unroll
        for (int kk = 0; kk < 64; kk++) {
            float4 pv = *(float4*)&St[kk * ATT_PITCH + r0];
            float4 vv = *(float4*)&Vs[kk * ATT_PITCH + c0];
            float pa[4] = {pv.x, pv.y, pv.z, pv.w};
            float va[4] = {vv.x, vv.y, vv.z, vv.w};
#pragma unroll
            for (int i = 0; i < 4; i++)
#pragma unroll
                for (int j = 0; j < 4; j++) o[i][j] += pa[i] * va[j];
        }
    }
    __syncthreads();

#pragma unroll
    for (int i = 0; i < 4; i++) {
        float inv = 1.f / lrow[r0 + i];
        size_t off = (size_t)(b * L_ + qbase + r0 + i) * D_ + h * DH_ + c0;
#pragma unroll
        for (int j = 0; j < 4; j++) {
            float val = o[i][j] * inv;
            __nv_bfloat16 hi = __float2bfloat16(val);
            ctxh[off + j] = hi;
            ctxl[off + j] = __float2bfloat16(val - __bfloat162float(hi));
        }
    }
}

// ---------------- SwiGLU -> bf16 hi/lo ----------------
__global__ void swiglu_kernel(const float* __restrict__ g,
                              __nv_bfloat16* __restrict__ swh,
                              __nv_bfloat16* __restrict__ swl) {
    int idx = blockIdx.x * blockDim.x + threadIdx.x;
    if (idx >= M_ * DFF_) return;
    int m = idx >> 12;
    int c = idx & 4095;
    float a  = g[(size_t)m * (2 * DFF_) + c];
    float b2 = g[(size_t)m * (2 * DFF_) + DFF_ + c];
    float sig = 1.0f / (1.0f + expf(-a));
    float v = a * sig * b2;
    __nv_bfloat16 hi = __float2bfloat16(v);
    swh[idx] = hi;
    swl[idx] = __float2bfloat16(v - __bfloat162float(hi));
}

// ---------------- host launch ----------------
extern "C" void kernel_launch(void* const* d_in, const int* in_sizes, int n_in,
                              void* d_out, int out_size) {
    const float* x_in = (const float*)d_in[0];
    const float* Wqkv = (const float*)d_in[2];
    const float* Wout = (const float*)d_in[3];
    const float* fc1  = (const float*)d_in[4];
    const float* fc2  = (const float*)d_in[5];
    const float* n1w  = (const float*)d_in[6];
    const float* n2w  = (const float*)d_in[7];
    const float* nfw  = (const float*)d_in[8];
    float* out = (float*)d_out;

    float *res, *qkv, *a, *g, *xb;
    __nv_bfloat16 *hnh, *hnl, *cth, *ctl, *swh, *swl;
    __nv_bfloat16 *wqh, *wql, *woh, *wol, *f1h, *f1l, *f2h, *f2l;
    cudaGetSymbolAddress((void**)&res, g_res);
    cudaGetSymbolAddress((void**)&qkv, g_qkv);
    cudaGetSymbolAddress((void**)&a,   g_a);
    cudaGetSymbolAddress((void**)&g,   g_gbuf);
    cudaGetSymbolAddress((void**)&xb,  g_x);
    cudaGetSymbolAddress((void**)&hnh, g_hn_hi);
    cudaGetSymbolAddress((void**)&hnl, g_hn_lo);
    cudaGetSymbolAddress((void**)&cth, g_ctx_hi);
    cudaGetSymbolAddress((void**)&ctl, g_ctx_lo);
    cudaGetSymbolAddress((void**)&swh, g_sw_hi);
    cudaGetSymbolAddress((void**)&swl, g_sw_lo);
    cudaGetSymbolAddress((void**)&wqh, g_wqkv_hi);
    cudaGetSymbolAddress((void**)&wql, g_wqkv_lo);
    cudaGetSymbolAddress((void**)&woh, g_wout_hi);
    cudaGetSymbolAddress((void**)&wol, g_wout_lo);
    cudaGetSymbolAddress((void**)&f1h, g_fc1_hi);
    cudaGetSymbolAddress((void**)&f1l, g_fc1_lo);
    cudaGetSymbolAddress((void**)&f2h, g_fc2_hi);
    cudaGetSymbolAddress((void**)&f2l, g_fc2_lo);

    cudaFuncSetAttribute(gemm_mma, cudaFuncAttributeMaxDynamicSharedMemorySize, GEMM_SMEM);
    cudaFuncSetAttribute(attn_flash, cudaFuncAttributeMaxDynamicSharedMemorySize, ATT_SMEM);

    // launches 1-4: weight cvts
    {
        int n;
        n = NL_*3*D_*D_;   cvt_kernel<<<(n+255)/256, 256>>>(Wqkv, wqh, wql, n);
        n = NL_*D_*D_;     cvt_kernel<<<(n+255)/256, 256>>>(Wout, woh, wol, n);
        n = NL_*2*DFF_*D_; cvt_kernel<<<(n+255)/256, 256>>>(fc1,  f1h, f1l, n);
        n = NL_*D_*DFF_;   cvt_kernel<<<(n+255)/256, 256>>>(fc2,  f2h, f2l, n);
    }

    const float* cur_x = x_in;
    for (int l = 0; l < NL_; l++) {
        // launch 5 (l=0): add_rms; launch 6 (l=0): gemm_mma  <- ncu -s 5 -c 1 target
        add_rms_kernel<1><<<M_, 256>>>(cur_x, res, res, hnh, hnl, nullptr,
                                       n1w + (size_t)l*D_, l > 0);
        gemm_mma<<<dim3(3*D_/128, M_/128), 256, GEMM_SMEM>>>(
            hnh, hnl, wqh + (size_t)l*3*D_*D_, wql + (size_t)l*3*D_*D_, qkv, 3*D_, D_);
        if (l == 0) rope_table_kernel<<<(L_*32 + 255)/256, 256>>>();
        rope_kernel<<<(M_*H_*32)/256, 256>>>(qkv);
        attn_flash<<<dim3(L_/64, H_, B_), 256, ATT_SMEM>>>(qkv, cth, ctl);
        gemm_mma<<<dim3(D_/128, M_/128), 256, GEMM_SMEM>>>(
            cth, ctl, woh + (size_t)l*D_*D_, wol + (size_t)l*D_*D_, a, D_, D_);
        add_rms_kernel<1><<<M_, 256>>>(a, res, res, hnh, hnl, nullptr,
                                       n2w + (size_t)l*D_, 1);
        gemm_mma<<<dim3(2*DFF_/128, M_/128), 256, GEMM_SMEM>>>(
            hnh, hnl, f1h + (size_t)l*2*DFF_*D_, f1l + (size_t)l*2*DFF_*D_, g, 2*DFF_, D_);
        swiglu_kernel<<<(M_*DFF_)/256, 256>>>(g, swh, swl);
        gemm_mma<<<dim3(D_/128, M_/128), 256, GEMM_SMEM>>>(
            swh, swl, f2h + (size_t)l*D_*DFF_, f2l + (size_t)l*D_*DFF_, xb, D_, DFF_);
        cur_x = xb;
    }
    add_rms_kernel<0><<<M_, 256>>>(cur_x, res, res, nullptr, nullptr, out, nfw, 1);
}

// round 9
// speedup vs baseline: 1.0682x; 1.0562x over previous
#include <cuda_runtime.h>
#include <cuda_bf16.h>
#include <math.h>
#include <cstdint>

// ---------------- problem constants ----------------
#define B_  2
#define L_  2048
#define D_  1024
#define NL_ 8
#define DFF_ 4096
#define H_  16
#define DH_ 64
#define WIN_ 1024
#define M_  (B_*L_)       // 4096 rows

// ---------------- scratch (device globals; no runtime alloc) ----------------
__device__ float g_res [M_*D_];
__device__ float g_qkv [M_*3*D_];
__device__ float g_a   [M_*D_];
__device__ float g_gbuf[M_*2*DFF_];
__device__ float g_x   [M_*D_];
__device__ float g_cos [L_*32];
__device__ float g_sin [L_*32];

__device__ __nv_bfloat16 g_hn_hi [M_*D_],   g_hn_lo [M_*D_];
__device__ __nv_bfloat16 g_ctx_hi[M_*D_],   g_ctx_lo[M_*D_];
__device__ __nv_bfloat16 g_sw_hi [M_*DFF_], g_sw_lo [M_*DFF_];

__device__ __nv_bfloat16 g_wqkv_hi[NL_*3*D_*D_],  g_wqkv_lo[NL_*3*D_*D_];
__device__ __nv_bfloat16 g_wout_hi[NL_*D_*D_],    g_wout_lo[NL_*D_*D_];
__device__ __nv_bfloat16 g_fc1_hi [NL_*2*DFF_*D_],g_fc1_lo [NL_*2*DFF_*D_];
__device__ __nv_bfloat16 g_fc2_hi [NL_*D_*DFF_],  g_fc2_lo [NL_*D_*DFF_];

// ---------------- helpers ----------------
__device__ __forceinline__ uint32_t smem_u32(const void* p) {
    uint32_t a;
    asm("{ .reg .u64 t; cvta.to.shared.u64 t, %1; cvt.u32.u64 %0, t; }" : "=r"(a) : "l"(p));
    return a;
}
__device__ __forceinline__ void cp16(uint32_t dst, const void* src) {
    asm volatile("cp.async.cg.shared.global [%0], [%1], 16;" :: "r"(dst), "l"(src));
}
#define CP_COMMIT() asm volatile("cp.async.commit_group;" ::: "memory")
#define CP_WAIT1()  asm volatile("cp.async.wait_group 1;" ::: "memory")

#define SWZ(x) ((x) ^ (((x) >> 3) & 0x70))

#define LDM_X4(r, a)                                                           \
    asm volatile("ldmatrix.sync.aligned.m8n8.x4.shared.b16 {%0,%1,%2,%3}, [%4];" \
        : "=r"((r)[0]), "=r"((r)[1]), "=r"((r)[2]), "=r"((r)[3]) : "r"(a))

#define MMA(d, a, b0, b1)                                                      \
    asm volatile("mma.sync.aligned.m16n8k16.row.col.f32.bf16.bf16.f32 "        \
        "{%0,%1,%2,%3},{%4,%5,%6,%7},{%8,%9},{%0,%1,%2,%3};"                   \
        : "+f"((d)[0]), "+f"((d)[1]), "+f"((d)[2]), "+f"((d)[3])               \
        : "r"((a)[0]), "r"((a)[1]), "r"((a)[2]), "r"((a)[3]), "r"(b0), "r"(b1))

// pack two floats -> bf16x2 (hi parts)
__device__ __forceinline__ uint32_t pack_bf2(float a, float b) {
    __nv_bfloat162 p = __floats2bfloat162_rn(a, b);
    return *(uint32_t*)&p;
}

// ---------------- HMMA GEMM: C[M,N] = A@W^T, split-bf16 (3 fused passes) -----
// CTA tile 128x128, BK=64, 256 threads, 3-stage cp.async pipeline (round-8 best).
#define TILE_BYTES 16384
#define STAGE_BYTES (4*TILE_BYTES)
#define GEMM_SMEM  (3*STAGE_BYTES)       // 196608

__device__ __forceinline__ void gemm_load_stage(
    uint32_t sb_stage,
    const __nv_bfloat16* __restrict__ Ah, const __nv_bfloat16* __restrict__ Al,
    const __nv_bfloat16* __restrict__ Wh, const __nv_bfloat16* __restrict__ Wl,
    int bm, int bn, int k0, int K, int tid)
{
    const __nv_bfloat16* bases[4] = { Ah + (size_t)bm * K, Al + (size_t)bm * K,
                                      Wh + (size_t)bn * K, Wl + (size_t)bn * K };
#pragma unroll
    for (int t = 0; t < 4; t++) {
        const __nv_bfloat16* base = bases[t];
#pragma unroll
        for (int q = 0; q < 4; q++) {
            int idx = tid + q * 256;
            int row = idx >> 3;
            int seg = idx & 7;
            const void* src = base + (size_t)row * K + k0 + seg * 8;
            uint32_t dst = sb_stage + t * TILE_BYTES + SWZ(row * 128 + seg * 16);
            cp16(dst, src);
        }
    }
}

__global__ __launch_bounds__(256, 1) void gemm_mma(
    const __nv_bfloat16* __restrict__ Ah, const __nv_bfloat16* __restrict__ Al,
    const __nv_bfloat16* __restrict__ Wh, const __nv_bfloat16* __restrict__ Wl,
    float* __restrict__ C, int N, int K)
{
    extern __shared__ char smem[];
    uint32_t sb = smem_u32(smem);
    int tid  = threadIdx.x;
    int lane = tid & 31;
    int wid  = tid >> 5;
    int warp_m = wid >> 2;
    int warp_n = wid & 3;
    int bm = blockIdx.y * 128;
    int bn = blockIdx.x * 128;

    float acc[4][4][4];
#pragma unroll
    for (int i = 0; i < 4; i++)
#pragma unroll
        for (int j = 0; j < 4; j++)
#pragma unroll
            for (int r = 0; r < 4; r++) acc[i][j][r] = 0.f;

    int a_row = warp_m * 64 + (lane & 15);
    int a_seg_off = (lane >> 4);
    int b_row = warp_n * 32 + (lane & 7) + ((lane & 16) >> 1);
    int b_seg_off = (lane >> 3) & 1;

    int chunks = K >> 6;
    gemm_load_stage(sb, Ah, Al, Wh, Wl, bm, bn, 0, K, tid);
    CP_COMMIT();
    if (chunks > 1) {
        gemm_load_stage(sb + STAGE_BYTES, Ah, Al, Wh, Wl, bm, bn, 64, K, tid);
    }
    CP_COMMIT();

    int st = 0;
    for (int ch = 0; ch < chunks; ch++) {
        CP_WAIT1();
        __syncthreads();
        if (ch + 2 < chunks) {
            int ns = st + 2; if (ns >= 3) ns -= 3;
            gemm_load_stage(sb + ns * STAGE_BYTES,
                            Ah, Al, Wh, Wl, bm, bn, (ch + 2) * 64, K, tid);
        }
        CP_COMMIT();

        uint32_t stage = sb + st * STAGE_BYTES;
#pragma unroll
        for (int ks = 0; ks < 4; ks++) {
            uint32_t ah[4][4], al[4][4], wb[2][4], wl[2][4];
#pragma unroll
            for (int i = 0; i < 4; i++) {
                int row = a_row + i * 16;
                uint32_t off = SWZ(row * 128 + (2 * ks + a_seg_off) * 16);
                LDM_X4(ah[i], stage + off);
                LDM_X4(al[i], stage + TILE_BYTES + off);
            }
#pragma unroll
            for (int j = 0; j < 2; j++) {
                int row = b_row + j * 16;
                uint32_t off = SWZ(row * 128 + (2 * ks + b_seg_off) * 16);
                LDM_X4(wb[j], stage + 2 * TILE_BYTES + off);
                LDM_X4(wl[j], stage + 3 * TILE_BYTES + off);
            }
#pragma unroll
            for (int i = 0; i < 4; i++)
#pragma unroll
                for (int j = 0; j < 4; j++)
                    MMA(acc[i][j], ah[i], wb[j >> 1][(j & 1) * 2], wb[j >> 1][(j & 1) * 2 + 1]);
#pragma unroll
            for (int i = 0; i < 4; i++)
#pragma unroll
                for (int j = 0; j < 4; j++)
                    MMA(acc[i][j], ah[i], wl[j >> 1][(j & 1) * 2], wl[j >> 1][(j & 1) * 2 + 1]);
#pragma unroll
            for (int i = 0; i < 4; i++)
#pragma unroll
                for (int j = 0; j < 4; j++)
                    MMA(acc[i][j], al[i], wb[j >> 1][(j & 1) * 2], wb[j >> 1][(j & 1) * 2 + 1]);
        }
        if (++st == 3) st = 0;
    }

#pragma unroll
    for (int i = 0; i < 4; i++) {
        int r0 = bm + warp_m * 64 + i * 16 + (lane >> 2);
#pragma unroll
        for (int j = 0; j < 4; j++) {
            int c = bn + warp_n * 32 + j * 8 + (lane & 3) * 2;
            *(float2*)&C[(size_t)r0 * N + c]       = make_float2(acc[i][j][0], acc[i][j][1]);
            *(float2*)&C[(size_t)(r0 + 8) * N + c] = make_float2(acc[i][j][2], acc[i][j][3]);
        }
    }
}

// ---------------- weight fp32 -> bf16 hi/lo split (vectorized x4) ----------------
__global__ void cvt_kernel(const float4* __restrict__ src,
                           uint2* __restrict__ hi,
                           uint2* __restrict__ lo, int n4) {
    int i = blockIdx.x * 256 + threadIdx.x;
    if (i >= n4) return;
    float4 v = src[i];
    __nv_bfloat16 h0 = __float2bfloat16(v.x), h1 = __float2bfloat16(v.y);
    __nv_bfloat16 h2 = __float2bfloat16(v.z), h3 = __float2bfloat16(v.w);
    uint2 ho, lw;
    {
        __nv_bfloat162 p01, p23;
        p01.x = h0; p01.y = h1; p23.x = h2; p23.y = h3;
        ho.x = *(uint32_t*)&p01; ho.y = *(uint32_t*)&p23;
    }
    lw.x = pack_bf2(v.x - __bfloat162float(h0), v.y - __bfloat162float(h1));
    lw.y = pack_bf2(v.z - __bfloat162float(h2), v.w - __bfloat162float(h3));
    hi[i] = ho;
    lo[i] = lw;
}

// ---------------- rope tables ----------------
__global__ void rope_table_kernel() {
    int idx = blockIdx.x * blockDim.x + threadIdx.x;
    if (idx >= L_ * 32) return;
    int pos = idx >> 5;
    int j = idx & 31;
    float e   = (float)(2 * j) / 64.0f;
    float inv = 1.0f / powf(10000.0f, e);
    float fr  = (float)pos * inv;
    g_cos[idx] = (float)cos((double)fr);
    g_sin[idx] = (float)sin((double)fr);
}

// ---------------- fused (x [+res]) -> res, rms*w -> hn (vectorized x4) ----
template<int BF>
__global__ void add_rms_kernel(const float* __restrict__ x,
                               const float* __restrict__ res_in,
                               float* __restrict__ res_out,
                               __nv_bfloat16* __restrict__ hh,
                               __nv_bfloat16* __restrict__ hl,
                               float* __restrict__ hf,
                               const float* __restrict__ w,
                               int useRes) {
    int row = blockIdx.x;
    int tid = threadIdx.x;
    int c = tid * 4;
    size_t base = (size_t)row * D_ + c;
    float4 v = *(const float4*)(x + base);
    if (useRes) {
        float4 r = *(const float4*)(res_in + base);
        v.x += r.x; v.y += r.y; v.z += r.z; v.w += r.w;
    }
    float ss = v.x * v.x + v.y * v.y + v.z * v.z + v.w * v.w;
#pragma unroll
    for (int o = 16; o; o >>= 1) ss += __shfl_xor_sync(0xffffffffu, ss, o);
    __shared__ float red[8];
    if ((tid & 31) == 0) red[tid >> 5] = ss;
    __syncthreads();
    float tot = 0.f;
#pragma unroll
    for (int i = 0; i < 8; i++) tot += red[i];
    float scale = rsqrtf(tot * (1.0f / (float)D_) + 1e-5f);

    *(float4*)(res_out + base) = v;
    float4 wv = *(const float4*)(w + c);
    float o0 = v.x * scale * wv.x, o1 = v.y * scale * wv.y;
    float o2 = v.z * scale * wv.z, o3 = v.w * scale * wv.w;
    if (BF) {
        __nv_bfloat16 h0 = __float2bfloat16(o0), h1 = __float2bfloat16(o1);
        __nv_bfloat16 h2 = __float2bfloat16(o2), h3 = __float2bfloat16(o3);
        uint2 ho, lw;
        __nv_bfloat162 p01, p23;
        p01.x = h0; p01.y = h1; p23.x = h2; p23.y = h3;
        ho.x = *(uint32_t*)&p01; ho.y = *(uint32_t*)&p23;
        lw.x = pack_bf2(o0 - __bfloat162float(h0), o1 - __bfloat162float(h1));
        lw.y = pack_bf2(o2 - __bfloat162float(h2), o3 - __bfloat162float(h3));
        *(uint2*)(hh + base) = ho;
        *(uint2*)(hl + base) = lw;
    } else {
        *(float4*)(hf + base) = make_float4(o0, o1, o2, o3);
    }
}

// ---------------- flash-tiled sliding-window attention + fused RoPE ----------
#define ATT_PITCH 68
#define ATT_SMEM ((4*64*ATT_PITCH + 192) * 4)

__global__ __launch_bounds__(256) void attn_flash(const float* __restrict__ qkv,
                                                  __nv_bfloat16* __restrict__ ctxh,
                                                  __nv_bfloat16* __restrict__ ctxl) {
    extern __shared__ float sm[];
    float* Qt = sm;
    float* Kt = sm + 64 * ATT_PITCH;
    float* Vs = sm + 2 * 64 * ATT_PITCH;
    float* St = sm + 3 * 64 * ATT_PITCH;
    float* mrow = sm + 4 * 64 * ATT_PITCH;
    float* lrow = mrow + 64;
    float* arow = mrow + 128;

    int qbase = blockIdx.x * 64;
    int h = blockIdx.y, b = blockIdx.z;
    int tid = threadIdx.x;
    const int RS = 3 * D_;
    const float* qk_base = qkv + (size_t)b * L_ * RS + h * DH_;

    // load Q: rope-rotate + scale + transpose
#pragma unroll
    for (int j = 0; j < 2; j++) {
        int idx = tid + 256 * j;           // 0..511
        int tok = idx >> 3;                // 64 tokens
        int p0  = (idx & 7) * 4;           // pair dims 0..28
        int pos = qbase + tok;
        const float* row = qk_base + (size_t)(qbase + tok) * RS;
        float4 u1 = *(const float4*)(row + p0);
        float4 u2 = *(const float4*)(row + p0 + 32);
        float4 cs = *(const float4*)&g_cos[pos * 32 + p0];
        float4 sn = *(const float4*)&g_sin[pos * 32 + p0];
        Qt[(p0 + 0) * ATT_PITCH + tok] = (u1.x * cs.x - u2.x * sn.x) * 0.125f;
        Qt[(p0 + 1) * ATT_PITCH + tok] = (u1.y * cs.y - u2.y * sn.y) * 0.125f;
        Qt[(p0 + 2) * ATT_PITCH + tok] = (u1.z * cs.z - u2.z * sn.z) * 0.125f;
        Qt[(p0 + 3) * ATT_PITCH + tok] = (u1.w * cs.w - u2.w * sn.w) * 0.125f;
        Qt[(p0 + 32) * ATT_PITCH + tok] = (u2.x * cs.x + u1.x * sn.x) * 0.125f;
        Qt[(p0 + 33) * ATT_PITCH + tok] = (u2.y * cs.y + u1.y * sn.y) * 0.125f;
        Qt[(p0 + 34) * ATT_PITCH + tok] = (u2.z * cs.z + u1.z * sn.z) * 0.125f;
        Qt[(p0 + 35) * ATT_PITCH + tok] = (u2.w * cs.w + u1.w * sn.w) * 0.125f;
    }
    if (tid < 64) { mrow[tid] = -INFINITY; lrow[tid] = 0.f; }

    int r0 = (tid >> 4) * 4;
    int c0 = (tid & 15) * 4;
    float o[4][4];
#pragma unroll
    for (int i = 0; i < 4; i++)
#pragma unroll
        for (int j = 0; j < 4; j++) o[i][j] = 0.f;

    int klo = qbase - (WIN_ - 1); if (klo < 0) klo = 0;
    int kt0 = klo & ~63;

    for (int kt = kt0; kt < qbase + 64; kt += 64) {
        __syncthreads();
        // K: rope-rotate + transpose
#pragma unroll
        for (int j = 0; j < 2; j++) {
            int idx = tid + 256 * j;
            int tok = idx >> 3;
            int p0  = (idx & 7) * 4;
            int pos = kt + tok;
            const float* row = qk_base + (size_t)(kt + tok) * RS + D_;
            float4 u1 = *(const float4*)(row + p0);
            float4 u2 = *(const float4*)(row + p0 + 32);
            float4 cs = *(const float4*)&g_cos[pos * 32 + p0];
            float4 sn = *(const float4*)&g_sin[pos * 32 + p0];
            Kt[(p0 + 0) * ATT_PITCH + tok] = u1.x * cs.x - u2.x * sn.x;
            Kt[(p0 + 1) * ATT_PITCH + tok] = u1.y * cs.y - u2.y * sn.y;
            Kt[(p0 + 2) * ATT_PITCH + tok] = u1.z * cs.z - u2.z * sn.z;
            Kt[(p0 + 3) * ATT_PITCH + tok] = u1.w * cs.w - u2.w * sn.w;
            Kt[(p0 + 32) * ATT_PITCH + tok] = u2.x * cs.x + u1.x * sn.x;
            Kt[(p0 + 33) * ATT_PITCH + tok] = u2.y * cs.y + u1.y * sn.y;
            Kt[(p0 + 34) * ATT_PITCH + tok] = u2.z * cs.z + u1.z * sn.z;
            Kt[(p0 + 35) * ATT_PITCH + tok] = u2.w * cs.w + u1.w * sn.w;
        }
        // V: plain copy
#pragma unroll
        for (int j = 0; j < 4; j++) {
            int idx = tid + 256 * j;
            int tok = idx >> 4;
            int d0  = (idx & 15) * 4;
            const float* row = qk_base + (size_t)(kt + tok) * RS + 2 * D_;
            float4 vv = *(const float4*)(row + d0);
            *(float4*)&Vs[tok * ATT_PITCH + d0] = vv;
        }
        __syncthreads();

        float s[4][4];
#pragma unroll
        for (int i = 0; i < 4; i++)
#pragma unroll
            for (int j = 0; j < 4; j++) s[i][j] = 0.f;
#pragma unroll
        for (int d = 0; d < 64; d++) {
            float4 qv = *(float4*)&Qt[d * ATT_PITCH + r0];
            float4 kv = *(float4*)&Kt[d * ATT_PITCH + c0];
            float qa[4] = {qv.x, qv.y, qv.z, qv.w};
            float ka[4] = {kv.x, kv.y, kv.z, kv.w};
#pragma unroll
            for (int i = 0; i < 4; i++)
#pragma unroll
                for (int j = 0; j < 4; j++) s[i][j] += qa[i] * ka[j];
        }
#pragma unroll
        for (int i = 0; i < 4; i++) {
            int qg = qbase + r0 + i;
#pragma unroll
            for (int j = 0; j < 4; j++) {
                int kg = kt + c0 + j;
                bool ok = (kg <= qg) && (kg >= qg - (WIN_ - 1));
                St[(c0 + j) * ATT_PITCH + r0 + i] = ok ? s[i][j] : -INFINITY;
            }
        }
        __syncthreads();

        {
            int row = tid >> 2;
            int part = tid & 3;
            float tmax = -INFINITY;
#pragma unroll
            for (int k = 0; k < 16; k++)
                tmax = fmaxf(tmax, St[(part * 16 + k) * ATT_PITCH + row]);
            tmax = fmaxf(tmax, __shfl_xor_sync(0xffffffffu, tmax, 1));
            tmax = fmaxf(tmax, __shfl_xor_sync(0xffffffffu, tmax, 2));
            float mold = mrow[row];
            float mnew = fmaxf(mold, tmax);
            float msafe = (mnew == -INFINITY) ? 0.f : mnew;
            float alpha = __expf(mold - msafe);
            float lsum = 0.f;
#pragma unroll
            for (int k = 0; k < 16; k++) {
                float* sp = &St[(part * 16 + k) * ATT_PITCH + row];
                float p = __expf(*sp - msafe);
                *sp = p;
                lsum += p;
            }
            lsum += __shfl_xor_sync(0xffffffffu, lsum, 1);
            lsum += __shfl_xor_sync(0xffffffffu, lsum, 2);
            if (part == 0) {
                mrow[row] = mnew;
                lrow[row] = alpha * lrow[row] + lsum;
                arow[row] = alpha;
            }
        }
        __syncthreads();

        float al[4];
#pragma unroll
        for (int i = 0; i < 4; i++) al[i] = arow[r0 + i];
#pragma unroll
        for (int i = 0; i < 4; i++)
#pragma unroll
            for (int j = 0; j < 4; j++) o[i][j] *= al[i];
#pragma unroll
        for (int kk = 0; kk < 64; kk++) {
            float4 pv = *(float4*)&St[kk * ATT_PITCH + r0];
            float4 vv = *(float4*)&Vs[kk * ATT_PITCH + c0];
            float pa[4] = {pv.x, pv.y, pv.z, pv.w};
            float va[4] = {vv.x, vv.y, vv.z, vv.w};
#pragma unroll
            for (int i = 0; i < 4; i++)
#pragma unroll
                for (int j = 0; j < 4; j++) o[i][j] += pa[i] * va[j];
        }
    }
    __syncthreads();

#pragma unroll
    for (int i = 0; i < 4; i++) {
        float inv = 1.f / lrow[r0 + i];
        size_t off = (size_t)(b * L_ + qbase + r0 + i) * D_ + h * DH_ + c0;
#pragma unroll
        for (int j = 0; j < 4; j++) {
            float val = o[i][j] * inv;
            __nv_bfloat16 hi = __float2bfloat16(val);
            ctxh[off + j] = hi;
            ctxl[off + j] = __float2bfloat16(val - __bfloat162float(hi));
        }
    }
}

// ---------------- SwiGLU -> bf16 hi/lo (vectorized x4) ----------------
__global__ void swiglu_kernel(const float* __restrict__ g,
                              uint2* __restrict__ swh,
                              uint2* __restrict__ swl) {
    int idx4 = blockIdx.x * blockDim.x + threadIdx.x;   // M_*DFF_/4 items
    if (idx4 >= M_ * DFF_ / 4) return;
    int base = idx4 * 4;
    int m = base >> 12;
    int c = base & 4095;
    const float* gr = g + (size_t)m * (2 * DFF_);
    float4 a  = *(const float4*)(gr + c);
    float4 b2 = *(const float4*)(gr + DFF_ + c);
    float v0 = a.x * b2.x / (1.0f + __expf(-a.x));
    float v1 = a.y * b2.y / (1.0f + __expf(-a.y));
    float v2 = a.z * b2.z / (1.0f + __expf(-a.z));
    float v3 = a.w * b2.w / (1.0f + __expf(-a.w));
    __nv_bfloat16 h0 = __float2bfloat16(v0), h1 = __float2bfloat16(v1);
    __nv_bfloat16 h2 = __float2bfloat16(v2), h3 = __float2bfloat16(v3);
    uint2 ho, lw;
    __nv_bfloat162 p01, p23;
    p01.x = h0; p01.y = h1; p23.x = h2; p23.y = h3;
    ho.x = *(uint32_t*)&p01; ho.y = *(uint32_t*)&p23;
    lw.x = pack_bf2(v0 - __bfloat162float(h0), v1 - __bfloat162float(h1));
    lw.y = pack_bf2(v2 - __bfloat162float(h2), v3 - __bfloat162float(h3));
    swh[idx4] = ho;
    swl[idx4] = lw;
}

// ---------------- host launch ----------------
extern "C" void kernel_launch(void* const* d_in, const int* in_sizes, int n_in,
                              void* d_out, int out_size) {
    const float* x_in = (const float*)d_in[0];
    const float* Wqkv = (const float*)d_in[2];
    const float* Wout = (const float*)d_in[3];
    const float* fc1  = (const float*)d_in[4];
    const float* fc2  = (const float*)d_in[5];
    const float* n1w  = (const float*)d_in[6];
    const float* n2w  = (const float*)d_in[7];
    const float* nfw  = (const float*)d_in[8];
    float* out = (float*)d_out;

    float *res, *qkv, *a, *g, *xb;
    __nv_bfloat16 *hnh, *hnl, *cth, *ctl, *swh, *swl;
    __nv_bfloat16 *wqh, *wql, *woh, *wol, *f1h, *f1l, *f2h, *f2l;
    cudaGetSymbolAddress((void**)&res, g_res);
    cudaGetSymbolAddress((void**)&qkv, g_qkv);
    cudaGetSymbolAddress((void**)&a,   g_a);
    cudaGetSymbolAddress((void**)&g,   g_gbuf);
    cudaGetSymbolAddress((void**)&xb,  g_x);
    cudaGetSymbolAddress((void**)&hnh, g_hn_hi);
    cudaGetSymbolAddress((void**)&hnl, g_hn_lo);
    cudaGetSymbolAddress((void**)&cth, g_ctx_hi);
    cudaGetSymbolAddress((void**)&ctl, g_ctx_lo);
    cudaGetSymbolAddress((void**)&swh, g_sw_hi);
    cudaGetSymbolAddress((void**)&swl, g_sw_lo);
    cudaGetSymbolAddress((void**)&wqh, g_wqkv_hi);
    cudaGetSymbolAddress((void**)&wql, g_wqkv_lo);
    cudaGetSymbolAddress((void**)&woh, g_wout_hi);
    cudaGetSymbolAddress((void**)&wol, g_wout_lo);
    cudaGetSymbolAddress((void**)&f1h, g_fc1_hi);
    cudaGetSymbolAddress((void**)&f1l, g_fc1_lo);
    cudaGetSymbolAddress((void**)&f2h, g_fc2_hi);
    cudaGetSymbolAddress((void**)&f2l, g_fc2_lo);

    cudaFuncSetAttribute(gemm_mma, cudaFuncAttributeMaxDynamicSharedMemorySize, GEMM_SMEM);
    cudaFuncSetAttribute(attn_flash, cudaFuncAttributeMaxDynamicSharedMemorySize, ATT_SMEM);

    {
        int n4;
        n4 = NL_*3*D_*D_/4;   cvt_kernel<<<(n4+255)/256, 256>>>((const float4*)Wqkv, (uint2*)wqh, (uint2*)wql, n4);
        n4 = NL_*D_*D_/4;     cvt_kernel<<<(n4+255)/256, 256>>>((const float4*)Wout, (uint2*)woh, (uint2*)wol, n4);
        n4 = NL_*2*DFF_*D_/4; cvt_kernel<<<(n4+255)/256, 256>>>((const float4*)fc1,  (uint2*)f1h, (uint2*)f1l, n4);
        n4 = NL_*D_*DFF_/4;   cvt_kernel<<<(n4+255)/256, 256>>>((const float4*)fc2,  (uint2*)f2h, (uint2*)f2l, n4);
    }
    rope_table_kernel<<<(L_*32 + 255)/256, 256>>>();

    const float* cur_x = x_in;
    for (int l = 0; l < NL_; l++) {
        add_rms_kernel<1><<<M_, 256>>>(cur_x, res, res, hnh, hnl, nullptr,
                                       n1w + (size_t)l*D_, l > 0);
        gemm_mma<<<dim3(3*D_/128, M_/128), 256, GEMM_SMEM>>>(
            hnh, hnl, wqh + (size_t)l*3*D_*D_, wql + (size_t)l*3*D_*D_, qkv, 3*D_, D_);
        attn_flash<<<dim3(L_/64, H_, B_), 256, ATT_SMEM>>>(qkv, cth, ctl);
        gemm_mma<<<dim3(D_/128, M_/128), 256, GEMM_SMEM>>>(
            cth, ctl, woh + (size_t)l*D_*D_, wol + (size_t)l*D_*D_, a, D_, D_);
        add_rms_kernel<1><<<M_, 256>>>(a, res, res, hnh, hnl, nullptr,
                                       n2w + (size_t)l*D_, 1);
        gemm_mma<<<dim3(2*DFF_/128, M_/128), 256, GEMM_SMEM>>>(
            hnh, hnl, f1h + (size_t)l*2*DFF_*D_, f1l + (size_t)l*2*DFF_*D_, g, 2*DFF_, D_);
        swiglu_kernel<<<(M_*DFF_/4 + 255)/256, 256>>>(g, (uint2*)swh, (uint2*)swl);
        gemm_mma<<<dim3(D_/128, M_/128), 256, GEMM_SMEM>>>(
            swh, swl, f2h + (size_t)l*D_*DFF_, f2l + (size_t)l*D_*DFF_, xb, D_, DFF_);
        cur_x = xb;
    }
    add_rms_kernel<0><<<M_, 256>>>(cur_x, res, res, nullptr, nullptr, out, nfw, 1);
}